// round 3
// baseline (speedup 1.0000x reference)
#include <cuda_runtime.h>
#include <math.h>
#include <stdint.h>

// ---------------------------------------------------------------------------
// SphereConv: Chebyshev graph conv (K=5) + BatchNorm(train) + ReLU
// x[B=8, Fin=64, V=49152], E = 9V = 442368 unsorted COO edges,
// weight[K=5,64,64], out[B,64,V] float32.
//
// The conv bias cancels exactly inside training-mode BatchNorm (it shifts the
// batch mean identically and leaves the variance unchanged), so it is never
// applied.
//
// Pipeline:
//   1) CSR build from unsorted COO (count / scan / scatter).
//   2) Transpose x -> T0 [B][V][F].
//   3) 4x SpMM (gather-only, warp per (b,v) row) for the Chebyshev recursion.
//   4) One fused fp32 GEMM over all 5 T_k with BN sum/sumsq partials.
//   5) BN finalize; fused normalize + ReLU + transpose back.
// ---------------------------------------------------------------------------

namespace {
constexpr int V  = 49152;
constexpr int E  = 442368;
constexpr int B  = 8;
constexpr int F  = 64;
constexpr int K  = 5;
constexpr long long BVF = (long long)B * V * F;   // 25,165,824
constexpr int NROWS = B * V;                      // 393,216
constexpr float EPS = 1e-5f;
}

__device__ float  g_T[(size_t)K * BVF];   // T_0..T_4, layout [k][b][v][f]
__device__ float  g_acc[(size_t)BVF];     // pre-BN output, layout [b][v][o]
__device__ int    g_ptr[V + 1];
__device__ int    g_cnt[V];
__device__ int    g_col[E];
__device__ float  g_val[E];
__device__ double g_dsum[F];
__device__ double g_dsq[F];
__device__ float  g_scale[F];
__device__ float  g_shift[F];

// ---------------- CSR build ----------------

__global__ void k_zero() {
    int i = blockIdx.x * blockDim.x + threadIdx.x;
    if (i < V) g_cnt[i] = 0;
    if (i < F) { g_dsum[i] = 0.0; g_dsq[i] = 0.0; }
}

__global__ void k_count(const int* __restrict__ rows) {
    int e = blockIdx.x * 256 + threadIdx.x;
    if (e < E) atomicAdd(&g_cnt[rows[e]], 1);
}

__global__ void k_scan() {
    __shared__ int part[1024];
    __shared__ int excl[1024];
    int t = threadIdx.x;
    const int CH = V / 1024;  // 48
    int base = t * CH;
    int s = 0;
    for (int i = 0; i < CH; i++) s += g_cnt[base + i];
    part[t] = s;
    __syncthreads();
    if (t == 0) {
        int run = 0;
        for (int i = 0; i < 1024; i++) { excl[i] = run; run += part[i]; }
    }
    __syncthreads();
    int run = excl[t];
    for (int i = 0; i < CH; i++) {
        g_ptr[base + i] = run;
        run += g_cnt[base + i];
        g_cnt[base + i] = 0;   // re-zero for scatter cursors
    }
    if (t == 0) g_ptr[V] = E;
}

__global__ void k_scatter(const int* __restrict__ rows,
                          const int* __restrict__ cols,
                          const float* __restrict__ vals) {
    int e = blockIdx.x * 256 + threadIdx.x;
    if (e < E) {
        int r = rows[e];
        int p = g_ptr[r] + atomicAdd(&g_cnt[r], 1);
        g_col[p] = cols[e];
        g_val[p] = vals[e];
    }
}

// ---------------- transpose x [B][F][V] -> T0 [B][V][F] ----------------

__global__ void k_transpose_x(const float* __restrict__ x) {
    __shared__ float tile[32][33];
    int b  = blockIdx.z;
    int f0 = blockIdx.y * 32;
    int v0 = blockIdx.x * 32;
    int tx = threadIdx.x, ty = threadIdx.y;  // (32,8)
    const float* xb = x + (size_t)b * F * V;
    #pragma unroll
    for (int j = 0; j < 32; j += 8)
        tile[ty + j][tx] = xb[(size_t)(f0 + ty + j) * V + v0 + tx];
    __syncthreads();
    float* Tb = g_T + (size_t)b * V * F;
    #pragma unroll
    for (int j = 0; j < 32; j += 8)
        Tb[(size_t)(v0 + ty + j) * F + f0 + tx] = tile[tx][ty + j];
}

// ---------------- SpMM: T_ko = L(T_kp)  (or 2*L(T_kp) - T_kpp) -------------

__global__ void k_spmm(int kp, int kpp, int ko, int first) {
    int lane = threadIdx.x & 31;
    int wid  = threadIdx.x >> 5;
    int v = blockIdx.x * 8 + wid;
    int b = blockIdx.y;
    const float* Tp = g_T + (size_t)kp * BVF + (size_t)b * V * F;
    int beg = g_ptr[v], end = g_ptr[v + 1];
    float ax = 0.f, ay = 0.f;
    int fo = lane * 2;
    int e = beg;
    // 2-way unroll for MLP in the gather chain
    for (; e + 1 < end; e += 2) {
        int   c0 = g_col[e];
        int   c1 = g_col[e + 1];
        float w0 = g_val[e];
        float w1 = g_val[e + 1];
        float2 t0 = *reinterpret_cast<const float2*>(Tp + (size_t)c0 * F + fo);
        float2 t1 = *reinterpret_cast<const float2*>(Tp + (size_t)c1 * F + fo);
        ax = fmaf(w0, t0.x, ax);
        ay = fmaf(w0, t0.y, ay);
        ax = fmaf(w1, t1.x, ax);
        ay = fmaf(w1, t1.y, ay);
    }
    if (e < end) {
        int   c = g_col[e];
        float w = g_val[e];
        float2 t = *reinterpret_cast<const float2*>(Tp + (size_t)c * F + fo);
        ax = fmaf(w, t.x, ax);
        ay = fmaf(w, t.y, ay);
    }
    size_t oi = ((size_t)b * V + v) * F + fo;
    float2 r;
    if (first) {
        r.x = ax; r.y = ay;
    } else {
        const float2 p = *reinterpret_cast<const float2*>(
            g_T + (size_t)kpp * BVF + oi);
        r.x = 2.f * ax - p.x;
        r.y = 2.f * ay - p.y;
    }
    *reinterpret_cast<float2*>(g_T + (size_t)ko * BVF + oi) = r;
}

// ---------------- fused GEMM: acc = sum_k T_k @ W_k, + BN partials ---------

__global__ void __launch_bounds__(256)
k_gemm(const float* __restrict__ Wt) {
    __shared__ float As[64][68];
    __shared__ float Ws[64][64];
    __shared__ float rsum[64];
    __shared__ float rsq[64];

    int tid = threadIdx.x;           // 256
    int tm  = tid >> 4;              // 0..15 -> rows tm*4..tm*4+3
    int to  = tid & 15;              // 0..15 -> cols to*4..to*4+3
    long long r0 = (long long)blockIdx.x * 64;

    float acc[4][4];
    #pragma unroll
    for (int a = 0; a < 4; a++)
        #pragma unroll
        for (int j = 0; j < 4; j++) acc[a][j] = 0.f;

    for (int k = 0; k < K; k++) {
        const float* Ak = g_T + (size_t)k * BVF + (size_t)r0 * 64;
        const float* Wk = Wt + k * 64 * 64;
        #pragma unroll
        for (int q = 0; q < 4; q++) {
            int idx = q * 256 + tid;
            int row = idx >> 4;
            int c4  = (idx & 15) * 4;
            *reinterpret_cast<float4*>(&As[row][c4]) =
                *reinterpret_cast<const float4*>(Ak + (size_t)row * 64 + c4);
            *reinterpret_cast<float4*>(&Ws[row][c4]) =
                *reinterpret_cast<const float4*>(Wk + row * 64 + c4);
        }
        __syncthreads();
        #pragma unroll 8
        for (int i = 0; i < 64; i++) {
            float a0 = As[tm * 4 + 0][i];
            float a1 = As[tm * 4 + 1][i];
            float a2 = As[tm * 4 + 2][i];
            float a3 = As[tm * 4 + 3][i];
            float4 w = *reinterpret_cast<const float4*>(&Ws[i][to * 4]);
            acc[0][0] = fmaf(a0, w.x, acc[0][0]);
            acc[0][1] = fmaf(a0, w.y, acc[0][1]);
            acc[0][2] = fmaf(a0, w.z, acc[0][2]);
            acc[0][3] = fmaf(a0, w.w, acc[0][3]);
            acc[1][0] = fmaf(a1, w.x, acc[1][0]);
            acc[1][1] = fmaf(a1, w.y, acc[1][1]);
            acc[1][2] = fmaf(a1, w.z, acc[1][2]);
            acc[1][3] = fmaf(a1, w.w, acc[1][3]);
            acc[2][0] = fmaf(a2, w.x, acc[2][0]);
            acc[2][1] = fmaf(a2, w.y, acc[2][1]);
            acc[2][2] = fmaf(a2, w.z, acc[2][2]);
            acc[2][3] = fmaf(a2, w.w, acc[2][3]);
            acc[3][0] = fmaf(a3, w.x, acc[3][0]);
            acc[3][1] = fmaf(a3, w.y, acc[3][1]);
            acc[3][2] = fmaf(a3, w.z, acc[3][2]);
            acc[3][3] = fmaf(a3, w.w, acc[3][3]);
        }
        __syncthreads();
    }

    if (tid < 64) { rsum[tid] = 0.f; rsq[tid] = 0.f; }
    __syncthreads();

    float* accp = g_acc + (size_t)r0 * 64;
    #pragma unroll
    for (int a = 0; a < 4; a++) {
        int m = tm * 4 + a;
        float4 o4 = make_float4(acc[a][0], acc[a][1], acc[a][2], acc[a][3]);
        *reinterpret_cast<float4*>(accp + (size_t)m * 64 + to * 4) = o4;
    }
    #pragma unroll
    for (int j = 0; j < 4; j++) {
        float s = 0.f, s2 = 0.f;
        #pragma unroll
        for (int a = 0; a < 4; a++) {
            float vv = acc[a][j];
            s += vv; s2 += vv * vv;
        }
        atomicAdd(&rsum[to * 4 + j], s);
        atomicAdd(&rsq[to * 4 + j], s2);
    }
    __syncthreads();
    if (tid < 64) {
        atomicAdd(&g_dsum[tid], (double)rsum[tid]);
        atomicAdd(&g_dsq[tid],  (double)rsq[tid]);
    }
}

// ---------------- BN finalize ----------------

__global__ void k_bnfin(const float* __restrict__ gamma,
                        const float* __restrict__ beta) {
    int o = threadIdx.x;
    double n = (double)NROWS;
    double mean = g_dsum[o] / n;
    double var  = g_dsq[o] / n - mean * mean;
    float sc = gamma[o] * rsqrtf((float)var + EPS);
    g_scale[o] = sc;
    g_shift[o] = beta[o] - (float)mean * sc;
}

// ---------------- normalize + ReLU + transpose to [B][F][V] ----------------

__global__ void k_final(float* __restrict__ out) {
    __shared__ float tile[32][33];
    int b  = blockIdx.z;
    int o0 = blockIdx.y * 32;
    int v0 = blockIdx.x * 32;
    int tx = threadIdx.x, ty = threadIdx.y;  // (32,8)
    float sc = g_scale[o0 + tx];
    float sh = g_shift[o0 + tx];
    const float* ap = g_acc + (size_t)b * V * 64;
    #pragma unroll
    for (int j = 0; j < 32; j += 8) {
        float val = ap[(size_t)(v0 + ty + j) * 64 + o0 + tx];
        tile[ty + j][tx] = fmaxf(fmaf(val, sc, sh), 0.f);
    }
    __syncthreads();
    float* ob = out + (size_t)b * F * V;
    #pragma unroll
    for (int j = 0; j < 32; j += 8)
        ob[(size_t)(o0 + ty + j) * V + v0 + tx] = tile[tx][ty + j];
}

// ---------------- launch ----------------

extern "C" void kernel_launch(void* const* d_in, const int* in_sizes, int n_in,
                              void* d_out, int out_size) {
    const float* x      = (const float*)d_in[0];
    const int*   rows   = (const int*)  d_in[1];
    const int*   cols   = (const int*)  d_in[2];
    const float* vals   = (const float*)d_in[3];
    const float* weight = (const float*)d_in[4];
    const float* gamma  = (const float*)d_in[6];
    const float* beta   = (const float*)d_in[7];
    float* out = (float*)d_out;

    k_zero<<<(V + 255) / 256, 256>>>();
    k_count<<<E / 256, 256>>>(rows);
    k_scan<<<1, 1024>>>();
    k_scatter<<<E / 256, 256>>>(rows, cols, vals);

    k_transpose_x<<<dim3(V / 32, F / 32, B), dim3(32, 8)>>>(x);

    dim3 sg(V / 8, B);
    k_spmm<<<sg, 256>>>(0, 0, 1, 1);   // T1 = L T0
    k_spmm<<<sg, 256>>>(1, 0, 2, 0);   // T2 = 2 L T1 - T0
    k_spmm<<<sg, 256>>>(2, 1, 3, 0);   // T3 = 2 L T2 - T1
    k_spmm<<<sg, 256>>>(3, 2, 4, 0);   // T4 = 2 L T3 - T2

    k_gemm<<<NROWS / 64, 256>>>(weight);

    k_bnfin<<<1, 64>>>(gamma, beta);
    k_final<<<dim3(V / 32, F / 32, B), dim3(32, 8)>>>(out);
}

// round 6
// speedup vs baseline: 1.2884x; 1.2884x over previous
#include <cuda_runtime.h>
#include <cuda_bf16.h>
#include <math.h>
#include <stdint.h>

// ---------------------------------------------------------------------------
// SphereConv: Chebyshev graph conv (K=5) + BatchNorm(train) + ReLU
// x[B=8, Fin=64, V=49152], E = 9V unsorted COO edges, weight[K=5,64,64],
// out[B,64,V] fp32.
//
// Conv bias cancels exactly inside training-mode BatchNorm -> never applied.
//
// NOTE: this toolchain targets compute_100 (no 'a' suffix) so tcgen05 is
// unavailable; the einsum uses warp-level mma.sync bf16 (sm_80+ path) with a
// bf16 hi/lo split (hi*hi + hi*lo + lo*hi, fp32 accum).
//
// Pipeline:
//   1) CSR build from unsorted COO (edges packed as int2(col, val-bits)).
//   2) Transpose x -> T0 [B][V][F]; W -> transposed bf16 hi/lo pairs.
//   3) 4x SpMM (coalesced gather, warp per row) for the Chebyshev recursion.
//   4) HMMA GEMM: acc[b][c][v] = sum_k T_k . W_k  (channel-major output).
//   5) Per-channel stats pass, BN finalize, elementwise normalize+ReLU.
// ---------------------------------------------------------------------------

namespace {
constexpr int V  = 49152;
constexpr int E  = 442368;
constexpr int B  = 8;
constexpr int F  = 64;
constexpr int K  = 5;
constexpr long long BVF = (long long)B * V * F;   // 25,165,824
constexpr int NROWS = B * V;                      // 393,216
constexpr float EPS = 1e-5f;

// SMEM tile layout for the GEMM (dynamic smem, byte offsets).
// Row stride 144 B (= 72 bf16): rows shift 16 B in bank space -> ldmatrix
// conflict-free, and every ldmatrix address stays 16B-aligned.
constexpr uint32_t TS = 144;
constexpr uint32_t OFF_AH = 0;                    // 128 x 144 = 18432 B
constexpr uint32_t OFF_AL = OFF_AH + 128 * TS;
constexpr uint32_t OFF_BH = OFF_AL + 128 * TS;    // 64 x 144 = 9216 B
constexpr uint32_t OFF_BL = OFF_BH + 64 * TS;
constexpr uint32_t GEMM_SMEM = OFF_BL + 64 * TS;  // 55296 B
}

__device__ float  g_T[(size_t)K * BVF];   // T_0..T_4, [k][b][v][f]
__device__ float  g_acc[(size_t)BVF];     // pre-BN output, [b][c][v] (channel-major)
__device__ int    g_ptr[V + 1];
__device__ int    g_cnt[V];
__device__ int2   g_edge[E];              // packed (col, val-bits)
__device__ uint2  g_Wh[5 * 1024];         // W^T hi bf16: [k][o(64)][i(64)] as uint2
__device__ uint2  g_Wl[5 * 1024];         // W^T lo bf16
__device__ double g_dsum[F];
__device__ double g_dsq[F];
__device__ float  g_scale[F];
__device__ float  g_shift[F];

// ---------------- PTX helpers (all sm_80-compatible) ----------------

__device__ __forceinline__ uint32_t smem_u32(const void* p) {
    uint32_t a;
    asm("{ .reg .u64 t; cvta.to.shared.u64 t, %1; cvt.u32.u64 %0, t; }"
        : "=r"(a) : "l"(p));
    return a;
}

__device__ __forceinline__ void ldsm_x4(uint32_t* r, uint32_t addr) {
    asm volatile("ldmatrix.sync.aligned.m8n8.x4.shared.b16 {%0,%1,%2,%3}, [%4];"
                 : "=r"(r[0]), "=r"(r[1]), "=r"(r[2]), "=r"(r[3]) : "r"(addr));
}
__device__ __forceinline__ void ldsm_x2(uint32_t* r, uint32_t addr) {
    asm volatile("ldmatrix.sync.aligned.m8n8.x2.shared.b16 {%0,%1}, [%2];"
                 : "=r"(r[0]), "=r"(r[1]) : "r"(addr));
}

__device__ __forceinline__ void mma16816(float* c, const uint32_t* a,
                                         const uint32_t* b) {
    asm volatile(
        "mma.sync.aligned.m16n8k16.row.col.f32.bf16.bf16.f32 "
        "{%0,%1,%2,%3}, {%4,%5,%6,%7}, {%8,%9}, {%0,%1,%2,%3};"
        : "+f"(c[0]), "+f"(c[1]), "+f"(c[2]), "+f"(c[3])
        : "r"(a[0]), "r"(a[1]), "r"(a[2]), "r"(a[3]), "r"(b[0]), "r"(b[1]));
}

// ---------------- CSR build ----------------

__global__ void k_zero() {
    int i = blockIdx.x * blockDim.x + threadIdx.x;
    if (i < V) g_cnt[i] = 0;
    if (i < F) { g_dsum[i] = 0.0; g_dsq[i] = 0.0; }
}

__global__ void k_count(const int* __restrict__ rows) {
    int e = blockIdx.x * 256 + threadIdx.x;
    if (e < E) atomicAdd(&g_cnt[rows[e]], 1);
}

__global__ void k_scan() {
    __shared__ int part[1024];
    __shared__ int excl[1024];
    int t = threadIdx.x;
    const int CH = V / 1024;  // 48
    int base = t * CH;
    int s = 0;
    for (int i = 0; i < CH; i++) s += g_cnt[base + i];
    part[t] = s;
    __syncthreads();
    if (t == 0) {
        int run = 0;
        for (int i = 0; i < 1024; i++) { excl[i] = run; run += part[i]; }
    }
    __syncthreads();
    int run = excl[t];
    for (int i = 0; i < CH; i++) {
        g_ptr[base + i] = run;
        run += g_cnt[base + i];
        g_cnt[base + i] = 0;
    }
    if (t == 0) g_ptr[V] = E;
}

__global__ void k_scatter(const int* __restrict__ rows,
                          const int* __restrict__ cols,
                          const float* __restrict__ vals) {
    int e = blockIdx.x * 256 + threadIdx.x;
    if (e < E) {
        int r = rows[e];
        int p = g_ptr[r] + atomicAdd(&g_cnt[r], 1);
        g_edge[p] = make_int2(cols[e], __float_as_int(vals[e]));
    }
}

// ---------------- W prep: weight[k][i][o] -> W^T bf16 hi/lo [k][o][i] -------

__global__ void k_wprep(const float* __restrict__ weight) {
    int idx = blockIdx.x * 256 + threadIdx.x;   // 5120 uint2 slots
    if (idx >= 5 * 1024) return;
    int k   = idx >> 10;
    int rem = idx & 1023;
    int o   = rem >> 4;
    int i0  = (rem & 15) * 4;
    const float* Wk = weight + k * 4096;
    float v0 = Wk[(i0 + 0) * 64 + o];
    float v1 = Wk[(i0 + 1) * 64 + o];
    float v2 = Wk[(i0 + 2) * 64 + o];
    float v3 = Wk[(i0 + 3) * 64 + o];
    __nv_bfloat162 h01 = __floats2bfloat162_rn(v0, v1);
    __nv_bfloat162 h23 = __floats2bfloat162_rn(v2, v3);
    float l0 = v0 - __bfloat162float(h01.x);
    float l1 = v1 - __bfloat162float(h01.y);
    float l2 = v2 - __bfloat162float(h23.x);
    float l3 = v3 - __bfloat162float(h23.y);
    __nv_bfloat162 lo01 = __floats2bfloat162_rn(l0, l1);
    __nv_bfloat162 lo23 = __floats2bfloat162_rn(l2, l3);
    g_Wh[idx] = make_uint2(*reinterpret_cast<uint32_t*>(&h01),
                           *reinterpret_cast<uint32_t*>(&h23));
    g_Wl[idx] = make_uint2(*reinterpret_cast<uint32_t*>(&lo01),
                           *reinterpret_cast<uint32_t*>(&lo23));
}

// ---------------- transpose x [B][F][V] -> T0 [B][V][F] ----------------

__global__ void k_transpose_x(const float* __restrict__ x) {
    __shared__ float tile[32][33];
    int b  = blockIdx.z;
    int f0 = blockIdx.y * 32;
    int v0 = blockIdx.x * 32;
    int tx = threadIdx.x, ty = threadIdx.y;  // (32,8)
    const float* xb = x + (size_t)b * F * V;
    #pragma unroll
    for (int j = 0; j < 32; j += 8)
        tile[ty + j][tx] = xb[(size_t)(f0 + ty + j) * V + v0 + tx];
    __syncthreads();
    float* Tb = g_T + (size_t)b * V * F;
    #pragma unroll
    for (int j = 0; j < 32; j += 8)
        Tb[(size_t)(v0 + ty + j) * F + f0 + tx] = tile[tx][ty + j];
}

// ---------------- SpMM: T_ko = L(T_kp)  (or 2*L(T_kp) - T_kpp) -------------

__global__ void k_spmm(int kp, int kpp, int ko, int first) {
    int lane = threadIdx.x & 31;
    int wid  = threadIdx.x >> 5;
    int v = blockIdx.x * 8 + wid;
    int b = blockIdx.y;
    const float* Tp = g_T + (size_t)kp * BVF + (size_t)b * V * F;
    int beg = g_ptr[v], end = g_ptr[v + 1];
    float ax = 0.f, ay = 0.f;
    int fo = lane * 2;
    int e = beg;
    for (; e + 1 < end; e += 2) {
        int2 e0 = g_edge[e];
        int2 e1 = g_edge[e + 1];
        float w0 = __int_as_float(e0.y);
        float w1 = __int_as_float(e1.y);
        float2 t0 = *reinterpret_cast<const float2*>(Tp + (size_t)e0.x * F + fo);
        float2 t1 = *reinterpret_cast<const float2*>(Tp + (size_t)e1.x * F + fo);
        ax = fmaf(w0, t0.x, ax);
        ay = fmaf(w0, t0.y, ay);
        ax = fmaf(w1, t1.x, ax);
        ay = fmaf(w1, t1.y, ay);
    }
    if (e < end) {
        int2 e0 = g_edge[e];
        float w = __int_as_float(e0.y);
        float2 t = *reinterpret_cast<const float2*>(Tp + (size_t)e0.x * F + fo);
        ax = fmaf(w, t.x, ax);
        ay = fmaf(w, t.y, ay);
    }
    size_t oi = ((size_t)b * V + v) * F + fo;
    float2 r;
    if (first) {
        r.x = ax; r.y = ay;
    } else {
        const float2 p = *reinterpret_cast<const float2*>(
            g_T + (size_t)kpp * BVF + oi);
        r.x = 2.f * ax - p.x;
        r.y = 2.f * ay - p.y;
    }
    *reinterpret_cast<float2*>(g_T + (size_t)ko * BVF + oi) = r;
}

// ---------------- HMMA GEMM: acc[b][c][v] = sum_k T_k @ W_k ----------------
// CTA tile 128(M) x 64(N); 8 warps, each 16 rows x 64 cols.
// bf16x3 split: D += Ah*Bh + Ah*Bl + Al*Bh, fp32 accumulators.

__global__ void __launch_bounds__(256)
k_gemm() {
    extern __shared__ char smem[];
    uint32_t sb = smem_u32(smem);
    int tid  = threadIdx.x;
    int warp = tid >> 5;
    int lane = tid & 31;

    long long r0 = (long long)blockIdx.x * 128;

    float acc[8][4];
    #pragma unroll
    for (int g = 0; g < 8; g++)
        #pragma unroll
        for (int j = 0; j < 4; j++) acc[g][j] = 0.f;

    // ldmatrix source addresses (per-lane, fixed across k-chunks)
    // A x4: tiles (rows0-7,k0),(rows8-15,k0),(rows0-7,k+8),(rows8-15,k+8)
    int at    = lane >> 3;           // 0..3
    int arow  = warp * 16 + (lane & 7) + (at & 1) * 8;
    uint32_t akoff = (uint32_t)(at >> 1) * 16;     // +8 bf16 = +16 B
    uint32_t aaddr_h = sb + OFF_AH + arow * TS + akoff;
    uint32_t aaddr_l = sb + OFF_AL + arow * TS + akoff;
    // B x2: tiles (n rows, k0), (n rows, k+8); lanes 16-31 mirror 0-15
    int bl    = lane & 15;
    int btile = bl >> 3;             // 0,1
    int brow  = bl & 7;              // n within group (base added per g)
    uint32_t bkoff = (uint32_t)btile * 16;

    for (int k = 0; k < K; k++) {
        // --- stage A tile: T_k[r0..r0+127][0..63] fp32 -> bf16 hi/lo ---
        const float* Ak = g_T + (size_t)k * BVF + (size_t)r0 * 64;
        #pragma unroll
        for (int q = 0; q < 8; q++) {
            int idx = q * 256 + tid;          // 0..2047 float4s
            int r   = idx >> 4;               // row 0..127
            int c4  = (idx & 15) * 4;         // col 0..60
            float4 v = *reinterpret_cast<const float4*>(Ak + (size_t)r * 64 + c4);
            __nv_bfloat162 h01 = __floats2bfloat162_rn(v.x, v.y);
            __nv_bfloat162 h23 = __floats2bfloat162_rn(v.z, v.w);
            float l0 = v.x - __bfloat162float(h01.x);
            float l1 = v.y - __bfloat162float(h01.y);
            float l2 = v.z - __bfloat162float(h23.x);
            float l3 = v.w - __bfloat162float(h23.y);
            __nv_bfloat162 lo01 = __floats2bfloat162_rn(l0, l1);
            __nv_bfloat162 lo23 = __floats2bfloat162_rn(l2, l3);
            uint32_t off = (uint32_t)r * TS + (uint32_t)c4 * 2;
            *reinterpret_cast<uint2*>(smem + OFF_AH + off) =
                make_uint2(*reinterpret_cast<uint32_t*>(&h01),
                           *reinterpret_cast<uint32_t*>(&h23));
            *reinterpret_cast<uint2*>(smem + OFF_AL + off) =
                make_uint2(*reinterpret_cast<uint32_t*>(&lo01),
                           *reinterpret_cast<uint32_t*>(&lo23));
        }
        // --- stage B tile: W^T_k hi/lo, 1024 uint2 each ---
        #pragma unroll
        for (int q = 0; q < 4; q++) {
            int idx = q * 256 + tid;          // 0..1023
            uint32_t off = (uint32_t)(idx >> 4) * TS + (uint32_t)(idx & 15) * 8;
            *reinterpret_cast<uint2*>(smem + OFF_BH + off) = g_Wh[k * 1024 + idx];
            *reinterpret_cast<uint2*>(smem + OFF_BL + off) = g_Wl[k * 1024 + idx];
        }
        __syncthreads();

        #pragma unroll
        for (int k16 = 0; k16 < 4; k16++) {
            uint32_t kb = (uint32_t)k16 * 32;  // 16 bf16 = 32 B per k16 step
            uint32_t ah[4], al[4];
            ldsm_x4(ah, aaddr_h + kb);
            ldsm_x4(al, aaddr_l + kb);
            #pragma unroll
            for (int g = 0; g < 8; g++) {
                uint32_t boff = (uint32_t)(g * 8 + brow) * TS + kb + bkoff;
                uint32_t bh[2], blr[2];
                ldsm_x2(bh,  sb + OFF_BH + boff);
                ldsm_x2(blr, sb + OFF_BL + boff);
                mma16816(acc[g], ah, bh);
                mma16816(acc[g], ah, blr);
                mma16816(acc[g], al, bh);
            }
        }
        __syncthreads();   // compute done before next k overwrites SMEM
    }

    // Epilogue: store channel-major. Thread holds rows (v0, v0+8), cols
    // g*8 + 2*(lane&3) + {0,1}. 8 consecutive v per c -> full sectors.
    long long rowb = r0 + warp * 16;
    int b  = (int)(rowb / V);          // constant per CTA (V % 128 == 0)
    int v0 = (int)(rowb % V) + (lane >> 2);
    float* ap = g_acc + (size_t)b * 64 * V;
    #pragma unroll
    for (int g = 0; g < 8; g++) {
        int c0 = g * 8 + 2 * (lane & 3);
        ap[(size_t)c0 * V + v0]           = acc[g][0];
        ap[(size_t)(c0 + 1) * V + v0]     = acc[g][1];
        ap[(size_t)c0 * V + v0 + 8]       = acc[g][2];
        ap[(size_t)(c0 + 1) * V + v0 + 8] = acc[g][3];
    }
}

// ---------------- BN stats over g_acc [b][c][v] ----------------

__global__ void __launch_bounds__(256)
k_stats() {
    __shared__ float ssum[8], ssq[8];
    int b = blockIdx.x >> 6;
    int c = blockIdx.x & 63;
    const float* p = g_acc + ((size_t)b * 64 + c) * V;
    int tid = threadIdx.x;
    float s = 0.f, s2 = 0.f;
    for (int i = tid * 4; i < V; i += 256 * 4) {
        float4 v = *reinterpret_cast<const float4*>(p + i);
        s  += v.x + v.y + v.z + v.w;
        s2 += v.x * v.x + v.y * v.y + v.z * v.z + v.w * v.w;
    }
    #pragma unroll
    for (int o = 16; o > 0; o >>= 1) {
        s  += __shfl_xor_sync(0xffffffffu, s,  o);
        s2 += __shfl_xor_sync(0xffffffffu, s2, o);
    }
    if ((tid & 31) == 0) { ssum[tid >> 5] = s; ssq[tid >> 5] = s2; }
    __syncthreads();
    if (tid == 0) {
        float ts = 0.f, tq = 0.f;
        #pragma unroll
        for (int w = 0; w < 8; w++) { ts += ssum[w]; tq += ssq[w]; }
        atomicAdd(&g_dsum[c], (double)ts);
        atomicAdd(&g_dsq[c],  (double)tq);
    }
}

// ---------------- BN finalize ----------------

__global__ void k_bnfin(const float* __restrict__ gamma,
                        const float* __restrict__ beta) {
    int o = threadIdx.x;
    double n = (double)NROWS;
    double mean = g_dsum[o] / n;
    double var  = g_dsq[o] / n - mean * mean;
    float sc = gamma[o] * rsqrtf((float)var + EPS);
    g_scale[o] = sc;
    g_shift[o] = beta[o] - (float)mean * sc;
}

// ---------------- elementwise normalize + ReLU (already channel-major) -----

__global__ void __launch_bounds__(256)
k_final(float* __restrict__ out) {
    long long n4 = BVF / 4;
    for (long long i4 = (long long)blockIdx.x * 256 + threadIdx.x; i4 < n4;
         i4 += (long long)gridDim.x * 256) {
        long long i = i4 * 4;
        int c = (int)((i / V) & 63);
        float sc = g_scale[c], sh = g_shift[c];
        float4 v = *reinterpret_cast<const float4*>(g_acc + i);
        v.x = fmaxf(fmaf(v.x, sc, sh), 0.f);
        v.y = fmaxf(fmaf(v.y, sc, sh), 0.f);
        v.z = fmaxf(fmaf(v.z, sc, sh), 0.f);
        v.w = fmaxf(fmaf(v.w, sc, sh), 0.f);
        *reinterpret_cast<float4*>(out + i) = v;
    }
}

// ---------------- launch ----------------

extern "C" void kernel_launch(void* const* d_in, const int* in_sizes, int n_in,
                              void* d_out, int out_size) {
    const float* x      = (const float*)d_in[0];
    const int*   rows   = (const int*)  d_in[1];
    const int*   cols   = (const int*)  d_in[2];
    const float* vals   = (const float*)d_in[3];
    const float* weight = (const float*)d_in[4];
    const float* gamma  = (const float*)d_in[6];
    const float* beta   = (const float*)d_in[7];
    float* out = (float*)d_out;

    cudaFuncSetAttribute(k_gemm, cudaFuncAttributeMaxDynamicSharedMemorySize,
                         GEMM_SMEM);

    k_zero<<<(V + 255) / 256, 256>>>();
    k_count<<<E / 256, 256>>>(rows);
    k_scan<<<1, 1024>>>();
    k_scatter<<<E / 256, 256>>>(rows, cols, vals);
    k_wprep<<<20, 256>>>(weight);

    k_transpose_x<<<dim3(V / 32, F / 32, B), dim3(32, 8)>>>(x);

    dim3 sg(V / 8, B);
    k_spmm<<<sg, 256>>>(0, 0, 1, 1);   // T1 = L T0
    k_spmm<<<sg, 256>>>(1, 0, 2, 0);   // T2 = 2 L T1 - T0
    k_spmm<<<sg, 256>>>(2, 1, 3, 0);   // T3 = 2 L T2 - T1
    k_spmm<<<sg, 256>>>(3, 2, 4, 0);   // T4 = 2 L T3 - T2

    k_gemm<<<NROWS / 128, 256, GEMM_SMEM>>>();

    k_stats<<<B * F, 256>>>();
    k_bnfin<<<1, 64>>>(gamma, beta);
    k_final<<<4096, 256>>>(out);
}

// round 8
// speedup vs baseline: 1.4005x; 1.0870x over previous
#include <cuda_runtime.h>
#include <cuda_bf16.h>
#include <cuda_fp16.h>
#include <math.h>
#include <stdint.h>

// ---------------------------------------------------------------------------
// SphereConv: Chebyshev graph conv (K=5) + BatchNorm(train) + ReLU
// x[B=8, Fin=64, V=49152], E = 9V unsorted COO edges, weight[K=5,64,64],
// out[B,64,V] fp32.
//
// Conv bias cancels exactly inside training-mode BatchNorm -> never applied.
//
// T_0..T_4 are stored in fp16: halves the SpMM gather traffic (the dominant
// cost, L2-bandwidth-bound) and the GEMM A-operand reads. The bf16 hi/lo
// split of a half value is exact, so the HMMA GEMM adds no further error.
//
// Pipeline:
//   1) CSR build from unsorted COO (edges packed as int2(col, val-bits)).
//   2) Transpose x -> T0 [B][V][F] (fp16); W -> transposed bf16 hi/lo pairs.
//   3) 4x SpMM (coalesced half2 gather, warp per row), fp32 accum, fp16 out.
//   4) HMMA GEMM (bf16x3): acc[b][c][v] = sum_k T_k . W_k (channel-major).
//   5) Per-channel stats pass, BN finalize, elementwise normalize+ReLU.
// ---------------------------------------------------------------------------

namespace {
constexpr int V  = 49152;
constexpr int E  = 442368;
constexpr int B  = 8;
constexpr int F  = 64;
constexpr int K  = 5;
constexpr long long BVF = (long long)B * V * F;   // 25,165,824
constexpr int NROWS = B * V;                      // 393,216
constexpr float EPS = 1e-5f;

// SMEM tile layout for the GEMM (dynamic smem, byte offsets).
// Row stride 144 B: rows shift 16 B in bank space -> ldmatrix conflict-free,
// and every ldmatrix address stays 16B-aligned.
constexpr uint32_t TS = 144;
constexpr uint32_t OFF_AH = 0;                    // 128 x 144 = 18432 B
constexpr uint32_t OFF_AL = OFF_AH + 128 * TS;
constexpr uint32_t OFF_BH = OFF_AL + 128 * TS;    // 64 x 144 = 9216 B
constexpr uint32_t OFF_BL = OFF_BH + 64 * TS;
constexpr uint32_t GEMM_SMEM = OFF_BL + 64 * TS;  // 55296 B
}

__device__ __half  g_Th[(size_t)K * BVF]; // T_0..T_4 fp16, [k][b][v][f]
__device__ float   g_acc[(size_t)BVF];    // pre-BN output, [b][c][v]
__device__ int     g_ptr[V + 1];
__device__ int     g_cnt[V];
__device__ int2    g_edge[E];             // packed (col, val-bits)
__device__ uint2   g_Wh[5 * 1024];        // W^T hi bf16: [k][o(64)][i(64)]
__device__ uint2   g_Wl[5 * 1024];        // W^T lo bf16
__device__ double  g_dsum[F];
__device__ double  g_dsq[F];
__device__ float   g_scale[F];
__device__ float   g_shift[F];

// ---------------- PTX helpers (all sm_80-compatible) ----------------

__device__ __forceinline__ uint32_t smem_u32(const void* p) {
    uint32_t a;
    asm("{ .reg .u64 t; cvta.to.shared.u64 t, %1; cvt.u32.u64 %0, t; }"
        : "=r"(a) : "l"(p));
    return a;
}

__device__ __forceinline__ void ldsm_x4(uint32_t* r, uint32_t addr) {
    asm volatile("ldmatrix.sync.aligned.m8n8.x4.shared.b16 {%0,%1,%2,%3}, [%4];"
                 : "=r"(r[0]), "=r"(r[1]), "=r"(r[2]), "=r"(r[3]) : "r"(addr));
}
__device__ __forceinline__ void ldsm_x2(uint32_t* r, uint32_t addr) {
    asm volatile("ldmatrix.sync.aligned.m8n8.x2.shared.b16 {%0,%1}, [%2];"
                 : "=r"(r[0]), "=r"(r[1]) : "r"(addr));
}

__device__ __forceinline__ void mma16816(float* c, const uint32_t* a,
                                         const uint32_t* b) {
    asm volatile(
        "mma.sync.aligned.m16n8k16.row.col.f32.bf16.bf16.f32 "
        "{%0,%1,%2,%3}, {%4,%5,%6,%7}, {%8,%9}, {%0,%1,%2,%3};"
        : "+f"(c[0]), "+f"(c[1]), "+f"(c[2]), "+f"(c[3])
        : "r"(a[0]), "r"(a[1]), "r"(a[2]), "r"(a[3]), "r"(b[0]), "r"(b[1]));
}

// ---------------- CSR build ----------------

__global__ void k_zero() {
    int i = blockIdx.x * blockDim.x + threadIdx.x;
    if (i < V) g_cnt[i] = 0;
    if (i < F) { g_dsum[i] = 0.0; g_dsq[i] = 0.0; }
}

__global__ void k_count(const int* __restrict__ rows) {
    int e = blockIdx.x * 256 + threadIdx.x;
    if (e < E) atomicAdd(&g_cnt[rows[e]], 1);
}

__global__ void k_scan() {
    __shared__ int part[1024];
    __shared__ int excl[1024];
    int t = threadIdx.x;
    const int CH = V / 1024;  // 48
    int base = t * CH;
    int s = 0;
    for (int i = 0; i < CH; i++) s += g_cnt[base + i];
    part[t] = s;
    __syncthreads();
    if (t == 0) {
        int run = 0;
        for (int i = 0; i < 1024; i++) { excl[i] = run; run += part[i]; }
    }
    __syncthreads();
    int run = excl[t];
    for (int i = 0; i < CH; i++) {
        g_ptr[base + i] = run;
        run += g_cnt[base + i];
        g_cnt[base + i] = 0;
    }
    if (t == 0) g_ptr[V] = E;
}

__global__ void k_scatter(const int* __restrict__ rows,
                          const int* __restrict__ cols,
                          const float* __restrict__ vals) {
    int e = blockIdx.x * 256 + threadIdx.x;
    if (e < E) {
        int r = rows[e];
        int p = g_ptr[r] + atomicAdd(&g_cnt[r], 1);
        g_edge[p] = make_int2(cols[e], __float_as_int(vals[e]));
    }
}

// ---------------- W prep: weight[k][i][o] -> W^T bf16 hi/lo [k][o][i] -------

__global__ void k_wprep(const float* __restrict__ weight) {
    int idx = blockIdx.x * 256 + threadIdx.x;   // 5120 uint2 slots
    if (idx >= 5 * 1024) return;
    int k   = idx >> 10;
    int rem = idx & 1023;
    int o   = rem >> 4;
    int i0  = (rem & 15) * 4;
    const float* Wk = weight + k * 4096;
    float v0 = Wk[(i0 + 0) * 64 + o];
    float v1 = Wk[(i0 + 1) * 64 + o];
    float v2 = Wk[(i0 + 2) * 64 + o];
    float v3 = Wk[(i0 + 3) * 64 + o];
    __nv_bfloat162 h01 = __floats2bfloat162_rn(v0, v1);
    __nv_bfloat162 h23 = __floats2bfloat162_rn(v2, v3);
    float l0 = v0 - __bfloat162float(h01.x);
    float l1 = v1 - __bfloat162float(h01.y);
    float l2 = v2 - __bfloat162float(h23.x);
    float l3 = v3 - __bfloat162float(h23.y);
    __nv_bfloat162 lo01 = __floats2bfloat162_rn(l0, l1);
    __nv_bfloat162 lo23 = __floats2bfloat162_rn(l2, l3);
    g_Wh[idx] = make_uint2(*reinterpret_cast<uint32_t*>(&h01),
                           *reinterpret_cast<uint32_t*>(&h23));
    g_Wl[idx] = make_uint2(*reinterpret_cast<uint32_t*>(&lo01),
                           *reinterpret_cast<uint32_t*>(&lo23));
}

// ---------------- transpose x [B][F][V] fp32 -> T0 [B][V][F] fp16 ----------

__global__ void k_transpose_x(const float* __restrict__ x) {
    __shared__ float tile[32][33];
    int b  = blockIdx.z;
    int f0 = blockIdx.y * 32;
    int v0 = blockIdx.x * 32;
    int tx = threadIdx.x, ty = threadIdx.y;  // (32,8)
    const float* xb = x + (size_t)b * F * V;
    #pragma unroll
    for (int j = 0; j < 32; j += 8)
        tile[ty + j][tx] = xb[(size_t)(f0 + ty + j) * V + v0 + tx];
    __syncthreads();
    __half* Tb = g_Th + (size_t)b * V * F;
    #pragma unroll
    for (int j = 0; j < 32; j += 8)
        Tb[(size_t)(v0 + ty + j) * F + f0 + tx] = __float2half_rn(tile[tx][ty + j]);
}

// ---------------- SpMM: T_ko = L(T_kp)  (or 2*L(T_kp) - T_kpp) -------------
// half2 gathers (one 128B line per warp per edge), fp32 accumulation.

__global__ void k_spmm(int kp, int kpp, int ko, int first) {
    int lane = threadIdx.x & 31;
    int wid  = threadIdx.x >> 5;
    int v = blockIdx.x * 8 + wid;
    int b = blockIdx.y;
    const __half* Tp = g_Th + (size_t)kp * BVF + (size_t)b * V * F;
    int beg = g_ptr[v], end = g_ptr[v + 1];
    float ax = 0.f, ay = 0.f;
    int fo = lane * 2;
    int e = beg;
    for (; e + 1 < end; e += 2) {
        int2 e0 = g_edge[e];
        int2 e1 = g_edge[e + 1];
        float w0 = __int_as_float(e0.y);
        float w1 = __int_as_float(e1.y);
        float2 t0 = __half22float2(
            *reinterpret_cast<const __half2*>(Tp + (size_t)e0.x * F + fo));
        float2 t1 = __half22float2(
            *reinterpret_cast<const __half2*>(Tp + (size_t)e1.x * F + fo));
        ax = fmaf(w0, t0.x, ax);
        ay = fmaf(w0, t0.y, ay);
        ax = fmaf(w1, t1.x, ax);
        ay = fmaf(w1, t1.y, ay);
    }
    if (e < end) {
        int2 e0 = g_edge[e];
        float w = __int_as_float(e0.y);
        float2 t = __half22float2(
            *reinterpret_cast<const __half2*>(Tp + (size_t)e0.x * F + fo));
        ax = fmaf(w, t.x, ax);
        ay = fmaf(w, t.y, ay);
    }
    size_t oi = ((size_t)b * V + v) * F + fo;
    float rx, ry;
    if (first) {
        rx = ax; ry = ay;
    } else {
        float2 p = __half22float2(
            *reinterpret_cast<const __half2*>(g_Th + (size_t)kpp * BVF + oi));
        rx = 2.f * ax - p.x;
        ry = 2.f * ay - p.y;
    }
    *reinterpret_cast<__half2*>(g_Th + (size_t)ko * BVF + oi) =
        __floats2half2_rn(rx, ry);
}

// ---------------- HMMA GEMM: acc[b][c][v] = sum_k T_k @ W_k ----------------
// CTA tile 128(M) x 64(N); 8 warps, each 16 rows x 64 cols.
// bf16x3 split: D += Ah*Bh + Ah*Bl + Al*Bh, fp32 accumulators.
// A source is fp16 -> hi/lo bf16 split is EXACT (11-bit mantissa <= 8+8).

__global__ void __launch_bounds__(256)
k_gemm() {
    extern __shared__ char smem[];
    uint32_t sb = smem_u32(smem);
    int tid  = threadIdx.x;
    int warp = tid >> 5;
    int lane = tid & 31;

    long long r0 = (long long)blockIdx.x * 128;

    float acc[8][4];
    #pragma unroll
    for (int g = 0; g < 8; g++)
        #pragma unroll
        for (int j = 0; j < 4; j++) acc[g][j] = 0.f;

    // ldmatrix source addresses (per-lane, fixed across k-chunks)
    int at    = lane >> 3;           // 0..3
    int arow  = warp * 16 + (lane & 7) + (at & 1) * 8;
    uint32_t akoff = (uint32_t)(at >> 1) * 16;     // +8 bf16 = +16 B
    uint32_t aaddr_h = sb + OFF_AH + arow * TS + akoff;
    uint32_t aaddr_l = sb + OFF_AL + arow * TS + akoff;
    int bl    = lane & 15;
    int btile = bl >> 3;             // 0,1
    int brow  = bl & 7;
    uint32_t bkoff = (uint32_t)btile * 16;

    for (int k = 0; k < K; k++) {
        // --- stage A tile: T_k[r0..r0+127][0..63] fp16 -> bf16 hi/lo ---
        const __half* Ak = g_Th + (size_t)k * BVF + (size_t)r0 * 64;
        #pragma unroll
        for (int q = 0; q < 8; q++) {
            int idx = q * 256 + tid;          // 0..2047 groups of 4 halves
            int r   = idx >> 4;               // row 0..127
            int c4  = (idx & 15) * 4;         // col 0..60
            uint2 hv = *reinterpret_cast<const uint2*>(Ak + (size_t)r * 64 + c4);
            float2 f01 = __half22float2(*reinterpret_cast<__half2*>(&hv.x));
            float2 f23 = __half22float2(*reinterpret_cast<__half2*>(&hv.y));
            __nv_bfloat162 h01 = __floats2bfloat162_rn(f01.x, f01.y);
            __nv_bfloat162 h23 = __floats2bfloat162_rn(f23.x, f23.y);
            float l0 = f01.x - __bfloat162float(h01.x);
            float l1 = f01.y - __bfloat162float(h01.y);
            float l2 = f23.x - __bfloat162float(h23.x);
            float l3 = f23.y - __bfloat162float(h23.y);
            __nv_bfloat162 lo01 = __floats2bfloat162_rn(l0, l1);
            __nv_bfloat162 lo23 = __floats2bfloat162_rn(l2, l3);
            uint32_t off = (uint32_t)r * TS + (uint32_t)c4 * 2;
            *reinterpret_cast<uint2*>(smem + OFF_AH + off) =
                make_uint2(*reinterpret_cast<uint32_t*>(&h01),
                           *reinterpret_cast<uint32_t*>(&h23));
            *reinterpret_cast<uint2*>(smem + OFF_AL + off) =
                make_uint2(*reinterpret_cast<uint32_t*>(&lo01),
                           *reinterpret_cast<uint32_t*>(&lo23));
        }
        // --- stage B tile: W^T_k hi/lo, 1024 uint2 each ---
        #pragma unroll
        for (int q = 0; q < 4; q++) {
            int idx = q * 256 + tid;          // 0..1023
            uint32_t off = (uint32_t)(idx >> 4) * TS + (uint32_t)(idx & 15) * 8;
            *reinterpret_cast<uint2*>(smem + OFF_BH + off) = g_Wh[k * 1024 + idx];
            *reinterpret_cast<uint2*>(smem + OFF_BL + off) = g_Wl[k * 1024 + idx];
        }
        __syncthreads();

        #pragma unroll
        for (int k16 = 0; k16 < 4; k16++) {
            uint32_t kb = (uint32_t)k16 * 32;  // 16 bf16 = 32 B per k16 step
            uint32_t ah[4], al[4];
            ldsm_x4(ah, aaddr_h + kb);
            ldsm_x4(al, aaddr_l + kb);
            #pragma unroll
            for (int g = 0; g < 8; g++) {
                uint32_t boff = (uint32_t)(g * 8 + brow) * TS + kb + bkoff;
                uint32_t bh[2], blr[2];
                ldsm_x2(bh,  sb + OFF_BH + boff);
                ldsm_x2(blr, sb + OFF_BL + boff);
                mma16816(acc[g], ah, bh);
                mma16816(acc[g], ah, blr);
                mma16816(acc[g], al, bh);
            }
        }
        __syncthreads();   // compute done before next k overwrites SMEM
    }

    // Epilogue: store channel-major. Thread holds rows (v0, v0+8), cols
    // g*8 + 2*(lane&3) + {0,1}.
    long long rowb = r0 + warp * 16;
    int b  = (int)(rowb / V);          // constant per CTA (V % 128 == 0)
    int v0 = (int)(rowb % V) + (lane >> 2);
    float* ap = g_acc + (size_t)b * 64 * V;
    #pragma unroll
    for (int g = 0; g < 8; g++) {
        int c0 = g * 8 + 2 * (lane & 3);
        ap[(size_t)c0 * V + v0]           = acc[g][0];
        ap[(size_t)(c0 + 1) * V + v0]     = acc[g][1];
        ap[(size_t)c0 * V + v0 + 8]       = acc[g][2];
        ap[(size_t)(c0 + 1) * V + v0 + 8] = acc[g][3];
    }
}

// ---------------- BN stats over g_acc [b][c][v] ----------------

__global__ void __launch_bounds__(256)
k_stats() {
    __shared__ float ssum[8], ssq[8];
    int b = blockIdx.x >> 6;
    int c = blockIdx.x & 63;
    const float* p = g_acc + ((size_t)b * 64 + c) * V;
    int tid = threadIdx.x;
    float s = 0.f, s2 = 0.f;
    for (int i = tid * 4; i < V; i += 256 * 4) {
        float4 v = *reinterpret_cast<const float4*>(p + i);
        s  += v.x + v.y + v.z + v.w;
        s2 += v.x * v.x + v.y * v.y + v.z * v.z + v.w * v.w;
    }
    #pragma unroll
    for (int o = 16; o > 0; o >>= 1) {
        s  += __shfl_xor_sync(0xffffffffu, s,  o);
        s2 += __shfl_xor_sync(0xffffffffu, s2, o);
    }
    if ((tid & 31) == 0) { ssum[tid >> 5] = s; ssq[tid >> 5] = s2; }
    __syncthreads();
    if (tid == 0) {
        float ts = 0.f, tq = 0.f;
        #pragma unroll
        for (int w = 0; w < 8; w++) { ts += ssum[w]; tq += ssq[w]; }
        atomicAdd(&g_dsum[c], (double)ts);
        atomicAdd(&g_dsq[c],  (double)tq);
    }
}

// ---------------- BN finalize ----------------

__global__ void k_bnfin(const float* __restrict__ gamma,
                        const float* __restrict__ beta) {
    int o = threadIdx.x;
    double n = (double)NROWS;
    double mean = g_dsum[o] / n;
    double var  = g_dsq[o] / n - mean * mean;
    float sc = gamma[o] * rsqrtf((float)var + EPS);
    g_scale[o] = sc;
    g_shift[o] = beta[o] - (float)mean * sc;
}

// ---------------- elementwise normalize + ReLU (channel-major) ----------

__global__ void __launch_bounds__(256)
k_final(float* __restrict__ out) {
    long long n4 = BVF / 4;
    for (long long i4 = (long long)blockIdx.x * 256 + threadIdx.x; i4 < n4;
         i4 += (long long)gridDim.x * 256) {
        long long i = i4 * 4;
        int c = (int)((i / V) & 63);
        float sc = g_scale[c], sh = g_shift[c];
        float4 v = *reinterpret_cast<const float4*>(g_acc + i);
        v.x = fmaxf(fmaf(v.x, sc, sh), 0.f);
        v.y = fmaxf(fmaf(v.y, sc, sh), 0.f);
        v.z = fmaxf(fmaf(v.z, sc, sh), 0.f);
        v.w = fmaxf(fmaf(v.w, sc, sh), 0.f);
        *reinterpret_cast<float4*>(out + i) = v;
    }
}

// ---------------- launch ----------------

extern "C" void kernel_launch(void* const* d_in, const int* in_sizes, int n_in,
                              void* d_out, int out_size) {
    const float* x      = (const float*)d_in[0];
    const int*   rows   = (const int*)  d_in[1];
    const int*   cols   = (const int*)  d_in[2];
    const float* vals   = (const float*)d_in[3];
    const float* weight = (const float*)d_in[4];
    const float* gamma  = (const float*)d_in[6];
    const float* beta   = (const float*)d_in[7];
    float* out = (float*)d_out;

    cudaFuncSetAttribute(k_gemm, cudaFuncAttributeMaxDynamicSharedMemorySize,
                         GEMM_SMEM);

    k_zero<<<(V + 255) / 256, 256>>>();
    k_count<<<E / 256, 256>>>(rows);
    k_scan<<<1, 1024>>>();
    k_scatter<<<E / 256, 256>>>(rows, cols, vals);
    k_wprep<<<20, 256>>>(weight);

    k_transpose_x<<<dim3(V / 32, F / 32, B), dim3(32, 8)>>>(x);

    dim3 sg(V / 8, B);
    k_spmm<<<sg, 256>>>(0, 0, 1, 1);   // T1 = L T0
    k_spmm<<<sg, 256>>>(1, 0, 2, 0);   // T2 = 2 L T1 - T0
    k_spmm<<<sg, 256>>>(2, 1, 3, 0);   // T3 = 2 L T2 - T1
    k_spmm<<<sg, 256>>>(3, 2, 4, 0);   // T4 = 2 L T3 - T2

    k_gemm<<<NROWS / 128, 256, GEMM_SMEM>>>();

    k_stats<<<B * F, 256>>>();
    k_bnfin<<<1, 64>>>(gamma, beta);
    k_final<<<4096, 256>>>(out);
}